// round 2
// baseline (speedup 1.0000x reference)
#include <cuda_runtime.h>

#define TOKENS 32768
#define DMODEL 2048
#define NEXP   64
#define TBLK   128      // tokens per block
#define KC     32       // k-chunk
#define NTH    256
#define NCHUNK (DMODEL / KC)   // 64
#define XT_LD  130      // xs_t row pitch (floats): even (8B-aligned LDS64 rows), 2 mod 32
#define WS_LD  68       // ws row pitch (floats), float4-aligned
#define LG_LD  68       // logits row pitch

typedef unsigned long long u64;

__device__ __forceinline__ void fma2(u64& d, u64 a, u64 b) {
    asm("fma.rn.f32x2 %0, %1, %2, %0;" : "+l"(d) : "l"(a), "l"(b));
}
__device__ __forceinline__ u64 pack2(float lo, float hi) {
    u64 r; asm("mov.b64 %0, {%1, %2};" : "=l"(r) : "f"(lo), "f"(hi)); return r;
}
__device__ __forceinline__ float2 unpack2(u64 v) {
    float lo, hi; asm("mov.b64 {%0, %1}, %2;" : "=f"(lo), "=f"(hi) : "l"(v));
    return make_float2(lo, hi);
}

__global__ __launch_bounds__(NTH)
void router_kernel(const float* __restrict__ x,
                   const float* __restrict__ w,
                   float* __restrict__ out)
{
    // Tile smem reused as logits scratch in the epilogue.
    __shared__ union {
        struct {
            float xs[KC * XT_LD];     // xs_t[k][token]  (k-major!)
            float ws[KC * WS_LD];     // ws[k][expert]   (transposed)
        } t;
        float logits[TBLK * LG_LD];   // logits[token][expert]
    } sm;
    __shared__ float inv_s[TBLK];

    const int tid = threadIdx.x;
    const int t0  = blockIdx.x * TBLK;
    const int tg  = tid & 15;     // token pairs at tg*2 + p*32, p=0..3
    const int eg  = tid >> 4;     // experts eg*4 .. eg*4+3

    // acc2[p][j]: packed fp32 pair over tokens (tg*2+p*32, +1), expert eg*4+j
    u64 acc2[4][4];
    #pragma unroll
    for (int p = 0; p < 4; p++)
        #pragma unroll
        for (int j = 0; j < 4; j++)
            acc2[p][j] = 0ull;

    // ---- register staging for global->smem pipeline ----
    float4 xr[4];   // x tile: 128 tok * 32 k floats / 256 thr = 4 float4 each
    float4 wr[2];   // w tile: 64 exp * 32 k floats / 256 thr = 2 float4 each

    // prefetch chunk 0
    {
        #pragma unroll
        for (int i = 0; i < 4; i++) {
            int f = tid + i * NTH;
            int row = f >> 3, c4 = f & 7;
            xr[i] = *(const float4*)&x[(size_t)(t0 + row) * DMODEL + c4 * 4];
        }
        #pragma unroll
        for (int i = 0; i < 2; i++) {
            int f = tid + i * NTH;
            int e = f >> 3, c4 = f & 7;
            wr[i] = *(const float4*)&w[(size_t)e * DMODEL + c4 * 4];
        }
    }

    for (int ch = 0; ch < NCHUNK; ++ch) {
        __syncthreads();   // previous chunk's compute done

        // regs -> smem. x stored k-major (transposed), w transposed to [k][e].
        #pragma unroll
        for (int i = 0; i < 4; i++) {
            int f = tid + i * NTH;
            int row = f >> 3, c4 = f & 7;
            sm.t.xs[(c4 * 4 + 0) * XT_LD + row] = xr[i].x;
            sm.t.xs[(c4 * 4 + 1) * XT_LD + row] = xr[i].y;
            sm.t.xs[(c4 * 4 + 2) * XT_LD + row] = xr[i].z;
            sm.t.xs[(c4 * 4 + 3) * XT_LD + row] = xr[i].w;
        }
        #pragma unroll
        for (int i = 0; i < 2; i++) {
            int f = tid + i * NTH;
            int e = f >> 3, c4 = f & 7;
            sm.t.ws[(c4 * 4 + 0) * WS_LD + e] = wr[i].x;
            sm.t.ws[(c4 * 4 + 1) * WS_LD + e] = wr[i].y;
            sm.t.ws[(c4 * 4 + 2) * WS_LD + e] = wr[i].z;
            sm.t.ws[(c4 * 4 + 3) * WS_LD + e] = wr[i].w;
        }
        __syncthreads();

        // prefetch next chunk while computing this one
        if (ch + 1 < NCHUNK) {
            const int k0 = (ch + 1) * KC;
            #pragma unroll
            for (int i = 0; i < 4; i++) {
                int f = tid + i * NTH;
                int row = f >> 3, c4 = f & 7;
                xr[i] = *(const float4*)&x[(size_t)(t0 + row) * DMODEL + k0 + c4 * 4];
            }
            #pragma unroll
            for (int i = 0; i < 2; i++) {
                int f = tid + i * NTH;
                int e = f >> 3, c4 = f & 7;
                wr[i] = *(const float4*)&w[(size_t)e * DMODEL + k0 + c4 * 4];
            }
        }

        // compute KC k-steps: 16 packed FMAs each (32 fp32 FMA/lane/k)
        #pragma unroll
        for (int k = 0; k < KC; k++) {
            u64 xp[4];
            #pragma unroll
            for (int p = 0; p < 4; p++)
                xp[p] = *(const u64*)&sm.t.xs[k * XT_LD + tg * 2 + p * 32];

            float4 wv = *(const float4*)&sm.t.ws[k * WS_LD + eg * 4];
            u64 wb[4];
            wb[0] = pack2(wv.x, wv.x);
            wb[1] = pack2(wv.y, wv.y);
            wb[2] = pack2(wv.z, wv.z);
            wb[3] = pack2(wv.w, wv.w);

            #pragma unroll
            for (int p = 0; p < 4; p++) {
                fma2(acc2[p][0], xp[p], wb[0]);
                fma2(acc2[p][1], xp[p], wb[1]);
                fma2(acc2[p][2], xp[p], wb[2]);
                fma2(acc2[p][3], xp[p], wb[3]);
            }
        }
    }

    // ---- epilogue ----
    __syncthreads();  // tile smem dead; reuse as logits
    #pragma unroll
    for (int p = 0; p < 4; p++) {
        int t = tg * 2 + p * 32;
        float2 v0 = unpack2(acc2[p][0]);
        float2 v1 = unpack2(acc2[p][1]);
        float2 v2 = unpack2(acc2[p][2]);
        float2 v3 = unpack2(acc2[p][3]);
        *(float4*)&sm.logits[(t + 0) * LG_LD + eg * 4] =
            make_float4(v0.x, v1.x, v2.x, v3.x);
        *(float4*)&sm.logits[(t + 1) * LG_LD + eg * 4] =
            make_float4(v0.y, v1.y, v2.y, v3.y);
    }
    __syncthreads();

    if (tid < TBLK) {
        const int t = tid;
        float* row = &sm.logits[t * LG_LD];

        // top-2 over logits (monotonic with probs). Strict > keeps lowest
        // index on exact ties, matching jax.lax.top_k.
        float m1 = -3.4e38f, m2 = -3.4e38f;
        int   i1 = 0,        i2 = 0;
        #pragma unroll
        for (int e = 0; e < NEXP; e++) {
            float v = row[e];
            if (v > m1)      { m2 = m1; i2 = i1; m1 = v; i1 = e; }
            else if (v > m2) { m2 = v; i2 = e; }
        }

        // exp + sum, exps written back in place for the probs pass
        float s = 0.0f;
        #pragma unroll
        for (int e = 0; e < NEXP; e++) {
            float ev = __expf(row[e] - m1);
            row[e] = ev;
            s += ev;
        }
        inv_s[t] = 1.0f / s;

        // gate weights: p1/(p1+p2) = 1/(1+e2) since e1 = exp(0) = 1
        float e2v = __expf(m2 - m1);
        float g1  = 1.0f / (1.0f + e2v);

        int gt = t0 + t;
        out[2 * gt + 0] = g1;
        out[2 * gt + 1] = e2v * g1;
        float* oidx = out + (size_t)2 * TOKENS;
        oidx[2 * gt + 0] = (float)i1;
        oidx[2 * gt + 1] = (float)i2;
    }
    __syncthreads();

    // cooperative coalesced probs write: probs[t][e] = exp[t][e] * inv_s[t]
    float* oprob = out + (size_t)4 * TOKENS;
    for (int f = tid; f < TBLK * (NEXP / 4); f += NTH) {
        int r = f >> 4, c4 = f & 15;
        float4 ev = *(const float4*)&sm.logits[r * LG_LD + c4 * 4];
        float inv = inv_s[r];
        float4 p = make_float4(ev.x * inv, ev.y * inv, ev.z * inv, ev.w * inv);
        *(float4*)&oprob[(size_t)(t0 + r) * NEXP + c4 * 4] = p;
    }
}

extern "C" void kernel_launch(void* const* d_in, const int* in_sizes, int n_in,
                              void* d_out, int out_size) {
    const float* x = (const float*)d_in[0];
    const float* w = (const float*)d_in[1];
    float* out = (float*)d_out;
    router_kernel<<<TOKENS / TBLK, NTH>>>(x, w, out);
}

// round 5
// speedup vs baseline: 2.5703x; 2.5703x over previous
#include <cuda_runtime.h>
#include <cuda_bf16.h>

#define TOKENS 32768
#define DMODEL 2048
#define NEXP   64
#define TBLK   128
#define KC     32
#define NCHUNK (DMODEL / KC)   // 64
#define NTH    256
#define XP     40              // smem pitch in bf16 elems (80B: 16B-aligned, bank-staggered)
#define LG_LD  68

typedef unsigned int u32;
typedef unsigned long long u64;

static __device__ __forceinline__ u32 smem_u32(const void* p) {
    u32 a;
    asm("{ .reg .u64 t; cvta.to.shared.u64 t, %1; cvt.u32.u64 %0, t; }" : "=r"(a) : "l"(p));
    return a;
}

// fp32 -> (bf16_hi, bf16_lo) split of 4 values, packed as u64 pairs
static __device__ __forceinline__ void split4(float4 v, u64& hi, u64& lo) {
    __nv_bfloat162 h01 = __float22bfloat162_rn(make_float2(v.x, v.y));
    __nv_bfloat162 h23 = __float22bfloat162_rn(make_float2(v.z, v.w));
    float2 f01 = __bfloat1622float2(h01);
    float2 f23 = __bfloat1622float2(h23);
    __nv_bfloat162 l01 = __float22bfloat162_rn(make_float2(v.x - f01.x, v.y - f01.y));
    __nv_bfloat162 l23 = __float22bfloat162_rn(make_float2(v.z - f23.x, v.w - f23.y));
    u32 a = *reinterpret_cast<u32*>(&h01);
    u32 b = *reinterpret_cast<u32*>(&h23);
    u32 c = *reinterpret_cast<u32*>(&l01);
    u32 d = *reinterpret_cast<u32*>(&l23);
    hi = (u64)a | ((u64)b << 32);
    lo = (u64)c | ((u64)d << 32);
}

#define LDSM_X4(R, addr)                                                      \
    asm volatile("ldmatrix.sync.aligned.m8n8.x4.shared.b16 {%0,%1,%2,%3}, [%4];" \
        : "=r"((R)[0]), "=r"((R)[1]), "=r"((R)[2]), "=r"((R)[3]) : "r"(addr))

#define MMA_BF16(C, A, B0, B1)                                                \
    asm volatile("mma.sync.aligned.m16n8k16.row.col.f32.bf16.bf16.f32 "       \
        "{%0,%1,%2,%3}, {%4,%5,%6,%7}, {%8,%9}, {%0,%1,%2,%3};"               \
        : "+f"((C)[0]), "+f"((C)[1]), "+f"((C)[2]), "+f"((C)[3])              \
        : "r"((A)[0]), "r"((A)[1]), "r"((A)[2]), "r"((A)[3]), "r"(B0), "r"(B1))

__global__ __launch_bounds__(NTH, 2)
void router_hmma_kernel(const float* __restrict__ x,
                        const float* __restrict__ w,
                        float* __restrict__ out)
{
    __shared__ union {
        struct {
            __align__(16) unsigned short xh[TBLK * XP];  // 10240 B
            __align__(16) unsigned short xl[TBLK * XP];
            __align__(16) unsigned short wh[NEXP * XP];  // 5120 B
            __align__(16) unsigned short wl[NEXP * XP];
        } t;
        float logits[TBLK * LG_LD];
    } sm;
    __shared__ float inv_s[TBLK];

    const int tid = threadIdx.x;
    const int wid = tid >> 5;
    const int lid = tid & 31;
    const int t0  = blockIdx.x * TBLK;

    // ---- global load geometry ----
    const int gr = tid >> 3;            // 0..31
    const int gc = tid & 7;             // float4 col in chunk
    const float* xbase = x + (size_t)(t0 + gr) * DMODEL + gc * 4;
    const float* wbase = w + (size_t)gr * DMODEL + gc * 4;
    const u32 soff = (u32)(gr * XP + gc * 4);  // elem offset in smem tile

    // ---- warp tile: 32 tokens x 32 experts ----
    const int wtok0 = (wid >> 1) * 32;
    const int wexp0 = (wid & 1) * 32;

    // ldmatrix lane address components (in elements)
    const int arow = (lid & 7) + ((lid >> 3) & 1) * 8;   // A: row within 16
    const int acol = ((lid >> 4) & 1) * 8;               // A: col-half
    const int brow = (lid & 7) + ((lid >> 4) & 1) * 8;   // B: expert within 16
    const int bcol = ((lid >> 3) & 1) * 8;               // B: k-half

    const u32 xh_b = smem_u32(sm.t.xh);
    const u32 xl_b = smem_u32(sm.t.xl);
    const u32 wh_b = smem_u32(sm.t.wh);
    const u32 wl_b = smem_u32(sm.t.wl);

    float acc[2][4][4];
    #pragma unroll
    for (int mt = 0; mt < 2; mt++)
        #pragma unroll
        for (int nt = 0; nt < 4; nt++)
            #pragma unroll
            for (int c = 0; c < 4; c++)
                acc[mt][nt][c] = 0.0f;

    float4 xr[4], wr[2];
    #pragma unroll
    for (int i = 0; i < 4; i++) xr[i] = *(const float4*)(xbase + (size_t)i * 32 * DMODEL);
    #pragma unroll
    for (int i = 0; i < 2; i++) wr[i] = *(const float4*)(wbase + (size_t)i * 32 * DMODEL);

    for (int ch = 0; ch < NCHUNK; ++ch) {
        if (ch) __syncthreads();   // previous chunk's compute done reading smem

        #pragma unroll
        for (int i = 0; i < 4; i++) {
            u64 hi, lo; split4(xr[i], hi, lo);
            u32 o = (soff + i * 32 * XP) * 2;
            *(u64*)((char*)sm.t.xh + o) = hi;
            *(u64*)((char*)sm.t.xl + o) = lo;
        }
        #pragma unroll
        for (int i = 0; i < 2; i++) {
            u64 hi, lo; split4(wr[i], hi, lo);
            u32 o = (soff + i * 32 * XP) * 2;
            *(u64*)((char*)sm.t.wh + o) = hi;
            *(u64*)((char*)sm.t.wl + o) = lo;
        }
        __syncthreads();

        if (ch + 1 < NCHUNK) {   // prefetch next chunk into regs during compute
            const int k0 = (ch + 1) * KC;
            #pragma unroll
            for (int i = 0; i < 4; i++)
                xr[i] = *(const float4*)(xbase + k0 + (size_t)i * 32 * DMODEL);
            #pragma unroll
            for (int i = 0; i < 2; i++)
                wr[i] = *(const float4*)(wbase + k0 + (size_t)i * 32 * DMODEL);
        }

        #pragma unroll
        for (int ks = 0; ks < KC / 16; ks++) {
            const int k0 = ks * 16;
            u32 ah[8], al[8], bh[8], bl[8];

            // A frags: 2 M-tiles (tokens wtok0, wtok0+16)
            #pragma unroll
            for (int mt = 0; mt < 2; mt++) {
                u32 ao = (u32)(((wtok0 + mt * 16 + arow) * XP + k0 + acol) * 2);
                LDSM_X4(ah + mt * 4, xh_b + ao);
                LDSM_X4(al + mt * 4, xl_b + ao);
            }
            // B frags: 4 N-tiles = 2 ldmatrix.x4 over 16 experts each
            #pragma unroll
            for (int ng = 0; ng < 2; ng++) {
                u32 bo = (u32)(((wexp0 + ng * 16 + brow) * XP + k0 + bcol) * 2);
                LDSM_X4(bh + ng * 4, wh_b + bo);
                LDSM_X4(bl + ng * 4, wl_b + bo);
            }

            #pragma unroll
            for (int mt = 0; mt < 2; mt++)
                #pragma unroll
                for (int nt = 0; nt < 4; nt++) {
                    u32 b0h = bh[nt * 2], b1h = bh[nt * 2 + 1];
                    MMA_BF16(acc[mt][nt], ah + mt * 4, b0h, b1h);          // hi*hi
                    MMA_BF16(acc[mt][nt], al + mt * 4, b0h, b1h);          // lo*hi
                    MMA_BF16(acc[mt][nt], ah + mt * 4, bl[nt * 2], bl[nt * 2 + 1]); // hi*lo
                }
        }
    }

    // ---- epilogue: accs -> smem logits ----
    __syncthreads();   // tile smem dead; reuse as logits
    {
        const int crow = lid >> 2;
        const int ccol = (lid & 3) * 2;
        #pragma unroll
        for (int mt = 0; mt < 2; mt++)
            #pragma unroll
            for (int nt = 0; nt < 4; nt++) {
                int tok = wtok0 + mt * 16 + crow;
                int ex  = wexp0 + nt * 8 + ccol;
                *(float2*)&sm.logits[tok * LG_LD + ex] =
                    make_float2(acc[mt][nt][0], acc[mt][nt][1]);
                *(float2*)&sm.logits[(tok + 8) * LG_LD + ex] =
                    make_float2(acc[mt][nt][2], acc[mt][nt][3]);
            }
    }
    __syncthreads();

    if (tid < TBLK) {
        const int t = tid;
        float* row = &sm.logits[t * LG_LD];

        float m1 = -3.4e38f, m2 = -3.4e38f;
        int   i1 = 0,        i2 = 0;
        #pragma unroll
        for (int e = 0; e < NEXP; e++) {
            float v = row[e];
            if (v > m1)      { m2 = m1; i2 = i1; m1 = v; i1 = e; }
            else if (v > m2) { m2 = v; i2 = e; }
        }

        float s = 0.0f;
        #pragma unroll
        for (int e = 0; e < NEXP; e++) {
            float ev = __expf(row[e] - m1);
            row[e] = ev;
            s += ev;
        }
        inv_s[t] = 1.0f / s;

        float e2v = __expf(m2 - m1);
        float g1  = 1.0f / (1.0f + e2v);

        int gt = t0 + t;
        out[2 * gt + 0] = g1;
        out[2 * gt + 1] = e2v * g1;
        float* oidx = out + (size_t)2 * TOKENS;
        oidx[2 * gt + 0] = (float)i1;
        oidx[2 * gt + 1] = (float)i2;
    }
    __syncthreads();

    float* oprob = out + (size_t)4 * TOKENS;
    for (int f = tid; f < TBLK * (NEXP / 4); f += NTH) {
        int r = f >> 4, c4 = f & 15;
        float4 ev = *(const float4*)&sm.logits[r * LG_LD + c4 * 4];
        float inv = inv_s[r];
        float4 p = make_float4(ev.x * inv, ev.y * inv, ev.z * inv, ev.w * inv);
        *(float4*)&oprob[(size_t)(t0 + r) * NEXP + c4 * 4] = p;
    }
}

extern "C" void kernel_launch(void* const* d_in, const int* in_sizes, int n_in,
                              void* d_out, int out_size) {
    const float* x = (const float*)d_in[0];
    const float* w = (const float*)d_in[1];
    float* out = (float*)d_out;
    router_hmma_kernel<<<TOKENS / TBLK, NTH>>>(x, w, out);
}